// round 11
// baseline (speedup 1.0000x reference)
#include <cuda_runtime.h>
#include <cuda_bf16.h>
#include <cstdint>

#define NEG_SLOPE 0.2f
#define STEP (2.0f / 255.0f)

typedef unsigned long long ull;

__device__ float g_asrc[131072];
__device__ float g_adst[131072];
// z split planes, k-major: [c][node], node = b<<16 | y<<8 | x
__device__ __nv_bfloat16 g_zh[64 * 131072];
__device__ __nv_bfloat16 g_zl[64 * 131072];

#define FMA2(d, a, b, c) \
    asm("fma.rn.f32x2 %0, %1, %2, %3;" : "=l"(d) : "l"(a), "l"(b), "l"(c))
#define DUP2(d, s) \
    asm("mov.b64 %0, {%1, %1};" : "=l"(d) : "r"(__float_as_uint(s)))
#define UNPACK2(lo, hi, s) do { \
    unsigned _ulo, _uhi; \
    asm("mov.b64 {%0, %1}, %2;" : "=r"(_ulo), "=r"(_uhi) : "l"(s)); \
    lo = __uint_as_float(_ulo); hi = __uint_as_float(_uhi); } while (0)

// ---------------------------------------------------------------------------
// K1: per-node a_src = xg.(W@att_src), a_dst = xg.(W@att_dst)   (unchanged)
// ---------------------------------------------------------------------------
__global__ __launch_bounds__(256) void gat_k1(
    const float* __restrict__ x,
    const float* __restrict__ pos_w,
    const float* __restrict__ pos_b,
    const float* __restrict__ lin_w,
    const float* __restrict__ att_src,
    const float* __restrict__ att_dst)
{
    __shared__ float swd[128];
    __shared__ float as_s[64], ad_s[64];
    __shared__ float pw0[64], pw1[64], pb_s[64];
    __shared__ float sc[6];

    const int tid = threadIdx.x;
    const int row = blockIdx.x;
    const int b = row >> 8;
    const int y = row & 255;

    if (tid < 64) {
        as_s[tid] = att_src[tid];
        ad_s[tid] = att_dst[tid];
        pw0[tid]  = pos_w[tid];
        pw1[tid]  = pos_w[64 + tid];
        pb_s[tid] = pos_b[tid];
    }
    __syncthreads();

    if (tid < 64) {
        float s = 0.0f, d = 0.0f;
        const float* lw = lin_w + tid * 64;
        #pragma unroll 8
        for (int co = 0; co < 64; co++) {
            float w = lw[co];
            s = fmaf(w, as_s[co], s);
            d = fmaf(w, ad_s[co], d);
        }
        swd[2 * tid]     = s;
        swd[2 * tid + 1] = d;
    }
    __syncthreads();

    if (tid < 6) {
        const int which = tid % 3;
        const int off   = (tid < 3) ? 0 : 1;
        const float* pv = (which == 0) ? pw0 : (which == 1) ? pw1 : pb_s;
        float acc = 0.0f;
        #pragma unroll 8
        for (int c = 0; c < 64; c++)
            acc = fmaf(pv[c], swd[2 * c + off], acc);
        sc[tid] = acc;
    }
    __syncthreads();

    const float py = -1.0f + (float)y * STEP;
    const float px = -1.0f + (float)tid * STEP;

    ull acc2 = 0ULL;
    const float* xp = x + (((size_t)b << 22) | ((size_t)y << 8)) + tid;
    const ull* wp = (const ull*)swd;
    #pragma unroll 8
    for (int c = 0; c < 64; c++) {
        float v = xp[(size_t)c << 16];
        ull vv; DUP2(vv, v);
        FMA2(acc2, vv, wp[c], acc2);
    }
    float s, d;
    UNPACK2(s, d, acc2);
    s += fmaf(py, sc[0], fmaf(px, sc[1], sc[2]));
    d += fmaf(py, sc[3], fmaf(px, sc[4], sc[5]));

    const int node = (b << 16) + (y << 8) + tid;
    g_asrc[node] = s;
    g_adst[node] = d;
}

// ---------------------------------------------------------------------------
// K2a: aggregation only. block = 128 x of one (b,y) row, 256 threads.
//   Phase A: alpha + PE sums -> smem. Phase B: R10 aggregation, z split to
//   bf16 hi/lo, stored DIRECTLY to global planes g_zh/g_zl [c][node].
//   ~6KB smem -> high occupancy; zero GEMM work.
// ---------------------------------------------------------------------------
__global__ __launch_bounds__(256) void gat_k2a(
    const float* __restrict__ x,
    const float* __restrict__ pos_w,
    const float* __restrict__ pos_b)
{
    __shared__ __align__(16) float alpha_sh[9 * 128];
    __shared__ __align__(16) float spy_sh[128], spx_sh[128];
    __shared__ float pw0[64], pw1[64], pb_s[64];

    const int tid  = threadIdx.x;
    const int lane = tid & 31;
    const int wid  = tid >> 5;
    const int blk  = blockIdx.x;       // 1024
    const int b  = blk >> 9;
    const int r  = blk & 511;
    const int y  = r >> 1;
    const int x0 = (r & 1) << 7;

    if (tid < 64) {
        pw0[tid]  = pos_w[tid];
        pw1[tid]  = pos_w[64 + tid];
        pb_s[tid] = pos_b[tid];
    }

    // ---- Phase A: alpha + PE sums (128 threads, one per x) ----
    if (tid < 128) {
        const int xl = tid;
        const int xd = x0 + xl;
        const float ad = g_adst[(b << 16) + (y << 8) + xd];
        float a[9];
        float m = -1e30f;
        #pragma unroll
        for (int ry = 0; ry < 3; ry++) {
            const int yy = y - 1 + ry;
            const bool rok = (unsigned)yy < 256u;
            #pragma unroll
            for (int cx = 0; cx < 3; cx++) {
                const int xs = xd - 1 + cx;
                float as = -1e30f;
                if (rok && (unsigned)xs < 256u)
                    as = g_asrc[(b << 16) + (yy << 8) + xs];
                float e = as + ad;
                e = (e >= 0.0f) ? e : NEG_SLOPE * e;
                a[ry * 3 + cx] = e;
                m = fmaxf(m, e);
            }
        }
        float ssum = 0.0f;
        #pragma unroll
        for (int j = 0; j < 9; j++) {
            float p = expf(a[j] - m);
            a[j] = p;
            ssum += p;
        }
        const float inv = 1.0f / ssum;
        float sumpy = 0.0f, sumpx = 0.0f;
        #pragma unroll
        for (int j = 0; j < 9; j++) {
            a[j] *= inv;
            alpha_sh[j * 128 + xl] = a[j];
            const float pyv = -1.0f + (float)(y - 1 + j / 3) * STEP;
            const float pxv = -1.0f + (float)(xd - 1 + j % 3) * STEP;
            sumpy = fmaf(a[j], pyv, sumpy);
            sumpx = fmaf(a[j], pxv, sumpx);
        }
        spy_sh[xl] = sumpy;
        spx_sh[xl] = sumpx;
    }
    __syncthreads();

    // ---- Phase B: aggregation, split to bf16, STG to planes ----
    {
        const float4 SPY = *(const float4*)&spy_sh[4 * lane];
        const float4 SPX = *(const float4*)&spx_sh[4 * lane];

        int ro[3];
        #pragma unroll
        for (int ry = 0; ry < 3; ry++) {
            int yy = y - 1 + ry;
            ro[ry] = (yy < 0 ? 0 : (yy > 255 ? 255 : yy)) << 8;
        }
        const int xlm = (x0 == 0) ? 0 : x0 - 1;
        const int xrm = (x0 + 128 > 255) ? 255 : x0 + 128;
        const int xoff = x0 + 4 * lane;

        const int c0 = wid * 8;
        const float* cbase = x + ((size_t)b << 22) + ((size_t)c0 << 16);
        const size_t node4 = (size_t)((b << 16) + (y << 8) + x0 + 4 * lane);

        #pragma unroll 2
        for (int ci = 0; ci < 8; ci++) {
            const int c = c0 + ci;
            const float* cp = cbase + ((size_t)ci << 16);

            float4 z;
            z.x = fmaf(pw0[c], SPY.x, fmaf(pw1[c], SPX.x, pb_s[c]));
            z.y = fmaf(pw0[c], SPY.y, fmaf(pw1[c], SPX.y, pb_s[c]));
            z.z = fmaf(pw0[c], SPY.z, fmaf(pw1[c], SPX.z, pb_s[c]));
            z.w = fmaf(pw0[c], SPY.w, fmaf(pw1[c], SPX.w, pb_s[c]));

            #pragma unroll
            for (int ry = 0; ry < 3; ry++) {
                const float* rp = cp + ro[ry];
                float4 v = *(const float4*)&rp[xoff];
                float l  = __shfl_up_sync(0xffffffffu, v.w, 1);
                float rr = __shfl_down_sync(0xffffffffu, v.x, 1);
                if (lane == 0)  l  = rp[xlm];
                if (lane == 31) rr = rp[xrm];
                const float4 a0 = *(const float4*)&alpha_sh[(ry * 3 + 0) * 128 + 4 * lane];
                const float4 a1 = *(const float4*)&alpha_sh[(ry * 3 + 1) * 128 + 4 * lane];
                const float4 a2 = *(const float4*)&alpha_sh[(ry * 3 + 2) * 128 + 4 * lane];
                z.x = fmaf(a0.x, l,   fmaf(a1.x, v.x, fmaf(a2.x, v.y, z.x)));
                z.y = fmaf(a0.y, v.x, fmaf(a1.y, v.y, fmaf(a2.y, v.z, z.y)));
                z.z = fmaf(a0.z, v.y, fmaf(a1.z, v.z, fmaf(a2.z, v.w, z.z)));
                z.w = fmaf(a0.w, v.z, fmaf(a1.w, v.w, fmaf(a2.w, rr,  z.w)));
            }

            // split and store straight to global planes
            __nv_bfloat162 h01 = __float22bfloat162_rn(make_float2(z.x, z.y));
            __nv_bfloat162 h23 = __float22bfloat162_rn(make_float2(z.z, z.w));
            float r0 = z.x - __bfloat162float(h01.x);
            float r1 = z.y - __bfloat162float(h01.y);
            float r2 = z.z - __bfloat162float(h23.x);
            float r3 = z.w - __bfloat162float(h23.y);
            __nv_bfloat162 l01 = __float22bfloat162_rn(make_float2(r0, r1));
            __nv_bfloat162 l23 = __float22bfloat162_rn(make_float2(r2, r3));
            uint2 hh; hh.x = *(uint32_t*)&h01; hh.y = *(uint32_t*)&h23;
            uint2 ll; ll.x = *(uint32_t*)&l01; ll.y = *(uint32_t*)&l23;
            const size_t idx = ((size_t)c << 17) + node4;
            *(uint2*)(g_zh + idx) = hh;
            *(uint2*)(g_zl + idx) = ll;
        }
    }
}

// ---------------------------------------------------------------------------
// mma helpers (base PTX, sm_80+)
// ---------------------------------------------------------------------------
__device__ __forceinline__ uint32_t smem_u32(const void* p) {
    uint32_t r;
    asm("{ .reg .u64 t; cvta.to.shared.u64 t, %1; cvt.u32.u64 %0, t; }"
        : "=r"(r) : "l"(p));
    return r;
}
__device__ __forceinline__ void ldm_x4(uint32_t* r, uint32_t a) {
    asm volatile("ldmatrix.sync.aligned.m8n8.x4.shared.b16 {%0,%1,%2,%3}, [%4];"
        : "=r"(r[0]), "=r"(r[1]), "=r"(r[2]), "=r"(r[3]) : "r"(a));
}
__device__ __forceinline__ void ldm_x4_t(uint32_t* r, uint32_t a) {
    asm volatile("ldmatrix.sync.aligned.m8n8.x4.trans.shared.b16 {%0,%1,%2,%3}, [%4];"
        : "=r"(r[0]), "=r"(r[1]), "=r"(r[2]), "=r"(r[3]) : "r"(a));
}
__device__ __forceinline__ void mma16816(float* c, const uint32_t* a,
                                         uint32_t b0, uint32_t b1) {
    asm volatile(
        "mma.sync.aligned.m16n8k16.row.col.f32.bf16.bf16.f32 "
        "{%0,%1,%2,%3}, {%4,%5,%6,%7}, {%8,%9}, {%0,%1,%2,%3};"
        : "+f"(c[0]), "+f"(c[1]), "+f"(c[2]), "+f"(c[3])
        : "r"(a[0]), "r"(a[1]), "r"(a[2]), "r"(a[3]), "r"(b0), "r"(b1));
}
__device__ __forceinline__ void cpasync16(uint32_t dst, const void* src) {
    asm volatile("cp.async.ca.shared.global [%0], [%1], 16;"
        :: "r"(dst), "l"(src) : "memory");
}

#define ZPITCH 272   // z tiles [c=64][x=128] bf16: 256B data + 16B pad
#define WPITCH 144   // W tiles [co=64][k=64] bf16: 128B data + 16B pad

// ---------------------------------------------------------------------------
// K2b: GEMM only. block = 128 tokens, 256 threads, 4 blocks/SM.
//   cp.async zh/zl tiles from planes; W hi/lo staged as R10; HMMA Phase C
//   and epilogue verbatim from R10.
// ---------------------------------------------------------------------------
__global__ __launch_bounds__(256, 4) void gat_k2b(
    const float* __restrict__ lin_w,
    const float* __restrict__ bias,
    float* __restrict__ out)
{
    __shared__ __align__(16) char tileblob[2 * 64 * ZPITCH];  // zh, zl; later staging
    __shared__ __align__(16) char wblob[2 * 64 * WPITCH];     // Wh, Wl
    __shared__ float b_s[64];

    const int tid  = threadIdx.x;
    const int lane = tid & 31;
    const int wid  = tid >> 5;
    const int blk  = blockIdx.x;       // 1024
    const int b  = blk >> 9;
    const int r  = blk & 511;
    const int y  = r >> 1;
    const int x0 = (r & 1) << 7;
    const int node0 = (b << 16) + (y << 8) + x0;

    char* zh_c = tileblob;
    char* zl_c = tileblob + 64 * ZPITCH;
    char* wh_c = wblob;
    char* wl_c = wblob + 64 * WPITCH;

    if (tid < 64) b_s[tid] = bias[tid];

    // ---- cp.async stage zh/zl tiles: 64 rows x 256B each ----
    {
        const uint32_t zh_s = smem_u32(zh_c);
        const uint32_t zl_s = smem_u32(zl_c);
        // 1024 16B-chunks per tile; thread does 4 per tile
        #pragma unroll
        for (int i = 0; i < 4; i++) {
            const int q = tid + i * 256;
            const int row = q >> 4;        // channel
            const int seg = q & 15;        // 16B segment within 256B row
            const size_t src_e = ((size_t)row << 17) + node0 + seg * 8;
            cpasync16(zh_s + row * ZPITCH + seg * 16, g_zh + src_e);
            cpasync16(zl_s + row * ZPITCH + seg * 16, g_zl + src_e);
        }
        asm volatile("cp.async.commit_group;" ::: "memory");
    }

    // ---- stage W hi/lo (overlaps with cp.async) ----
    {
        const int co = tid & 63;
        const int kq = tid >> 6;
        const float* wp = lin_w + co;
        #pragma unroll
        for (int j = 0; j < 8; j++) {
            const int k0 = kq * 16 + 2 * j;
            float w0 = wp[(size_t)k0 * 64];
            float w1 = wp[(size_t)(k0 + 1) * 64];
            __nv_bfloat162 h = __float22bfloat162_rn(make_float2(w0, w1));
            *(uint32_t*)(wh_c + co * WPITCH + k0 * 2) = *(uint32_t*)&h;
            float r0 = w0 - __bfloat162float(h.x);
            float r1 = w1 - __bfloat162float(h.y);
            __nv_bfloat162 l = __float22bfloat162_rn(make_float2(r0, r1));
            *(uint32_t*)(wl_c + co * WPITCH + k0 * 2) = *(uint32_t*)&l;
        }
    }

    asm volatile("cp.async.wait_group 0;" ::: "memory");
    __syncthreads();

    // ---- HMMA GEMM (R10 Phase C) ----
    const int m0 = (wid & 3) << 4;
    const int nb = (wid >> 2) << 6;

    const uint32_t zh_b = smem_u32(zh_c);
    const uint32_t zl_b = smem_u32(zl_c);
    const uint32_t wh_b = smem_u32(wh_c);
    const uint32_t wl_b = smem_u32(wl_c);

    const uint32_t w_row = (uint32_t)(m0 + (lane & 15)) * WPITCH;
    const uint32_t w_kad = ((lane >> 4) << 3) * 2;
    const uint32_t z_kro = (uint32_t)(lane & 15) * ZPITCH;
    const uint32_t z_nad = ((lane >> 4) << 3) * 2;

    float acc[8][4];
    #pragma unroll
    for (int i = 0; i < 8; i++)
        #pragma unroll
        for (int j = 0; j < 4; j++) acc[i][j] = 0.0f;

    #pragma unroll
    for (int ks = 0; ks < 4; ks++) {
        const int k0 = ks << 4;
        uint32_t ah[4], al[4];
        ldm_x4(ah, wh_b + w_row + (uint32_t)k0 * 2 + w_kad);
        ldm_x4(al, wl_b + w_row + (uint32_t)k0 * 2 + w_kad);

        #pragma unroll
        for (int np = 0; np < 4; np++) {
            const uint32_t n0 = nb + (np << 4);
            const uint32_t zoff = (uint32_t)k0 * ZPITCH + z_kro + n0 * 2 + z_nad;
            uint32_t bh[4], bl[4];
            ldm_x4_t(bh, zh_b + zoff);
            ldm_x4_t(bl, zl_b + zoff);
            mma16816(acc[2 * np],     ah, bh[0], bh[1]);
            mma16816(acc[2 * np + 1], ah, bh[2], bh[3]);
            mma16816(acc[2 * np],     ah, bl[0], bl[1]);
            mma16816(acc[2 * np + 1], ah, bl[2], bl[3]);
            mma16816(acc[2 * np],     al, bh[0], bh[1]);
            mma16816(acc[2 * np + 1], al, bh[2], bh[3]);
        }
    }
    __syncthreads();

    // ---- epilogue: frags -> staging [co][x] (pitch 132 floats) ----
    float* stage = (float*)tileblob;
    {
        const int co_r = m0 + (lane >> 2);
        #pragma unroll
        for (int nt = 0; nt < 8; nt++) {
            const int xb = nb + nt * 8 + 2 * (lane & 3);
            *(float2*)&stage[co_r * 132 + xb]       = make_float2(acc[nt][0], acc[nt][1]);
            *(float2*)&stage[(co_r + 8) * 132 + xb] = make_float2(acc[nt][2], acc[nt][3]);
        }
    }
    __syncthreads();

    {
        const int xq = lane;
        float* ob = out + ((size_t)b << 22) + (y << 8) + x0 + 4 * xq;
        #pragma unroll
        for (int it = 0; it < 8; it++) {
            const int co = wid + it * 8;
            float4 v = *(const float4*)&stage[co * 132 + 4 * xq];
            const float bv = b_s[co];
            v.x += bv; v.y += bv; v.z += bv; v.w += bv;
            *(float4*)(ob + ((size_t)co << 16)) = v;
        }
    }
}

// ---------------------------------------------------------------------------
extern "C" void kernel_launch(void* const* d_in, const int* in_sizes, int n_in,
                              void* d_out, int out_size)
{
    const float* x       = (const float*)d_in[0];
    const float* pos_w   = (const float*)d_in[1];
    const float* pos_b   = (const float*)d_in[2];
    const float* lin_w   = (const float*)d_in[3];
    const float* att_src = (const float*)d_in[4];
    const float* att_dst = (const float*)d_in[5];
    const float* bias    = (const float*)d_in[6];
    float* out = (float*)d_out;

    gat_k1<<<512, 256>>>(x, pos_w, pos_b, lin_w, att_src, att_dst);
    gat_k2a<<<1024, 256>>>(x, pos_w, pos_b);
    gat_k2b<<<1024, 256>>>(lin_w, bias, out);
}

// round 12
// speedup vs baseline: 1.6654x; 1.6654x over previous
#include <cuda_runtime.h>
#include <cuda_bf16.h>
#include <cstdint>

#define NEG_SLOPE 0.2f
#define STEP (2.0f / 255.0f)

typedef unsigned long long ull;

__device__ float g_asrc[131072];
__device__ float g_adst[131072];

#define FMA2(d, a, b, c) \
    asm("fma.rn.f32x2 %0, %1, %2, %3;" : "=l"(d) : "l"(a), "l"(b), "l"(c))
#define DUP2(d, s) \
    asm("mov.b64 %0, {%1, %1};" : "=l"(d) : "r"(__float_as_uint(s)))
#define UNPACK2(lo, hi, s) do { \
    unsigned _ulo, _uhi; \
    asm("mov.b64 {%0, %1}, %2;" : "=r"(_ulo), "=r"(_uhi) : "l"(s)); \
    lo = __uint_as_float(_ulo); hi = __uint_as_float(_uhi); } while (0)

// ---------------------------------------------------------------------------
// K1: per-node a_src = xg.(W@att_src), a_dst = xg.(W@att_dst)   (unchanged)
// ---------------------------------------------------------------------------
__global__ __launch_bounds__(256) void gat_k1(
    const float* __restrict__ x,
    const float* __restrict__ pos_w,
    const float* __restrict__ pos_b,
    const float* __restrict__ lin_w,
    const float* __restrict__ att_src,
    const float* __restrict__ att_dst)
{
    __shared__ float swd[128];
    __shared__ float as_s[64], ad_s[64];
    __shared__ float pw0[64], pw1[64], pb_s[64];
    __shared__ float sc[6];

    const int tid = threadIdx.x;
    const int row = blockIdx.x;
    const int b = row >> 8;
    const int y = row & 255;

    if (tid < 64) {
        as_s[tid] = att_src[tid];
        ad_s[tid] = att_dst[tid];
        pw0[tid]  = pos_w[tid];
        pw1[tid]  = pos_w[64 + tid];
        pb_s[tid] = pos_b[tid];
    }
    __syncthreads();

    if (tid < 64) {
        float s = 0.0f, d = 0.0f;
        const float* lw = lin_w + tid * 64;
        #pragma unroll 8
        for (int co = 0; co < 64; co++) {
            float w = lw[co];
            s = fmaf(w, as_s[co], s);
            d = fmaf(w, ad_s[co], d);
        }
        swd[2 * tid]     = s;
        swd[2 * tid + 1] = d;
    }
    __syncthreads();

    if (tid < 6) {
        const int which = tid % 3;
        const int off   = (tid < 3) ? 0 : 1;
        const float* pv = (which == 0) ? pw0 : (which == 1) ? pw1 : pb_s;
        float acc = 0.0f;
        #pragma unroll 8
        for (int c = 0; c < 64; c++)
            acc = fmaf(pv[c], swd[2 * c + off], acc);
        sc[tid] = acc;
    }
    __syncthreads();

    const float py = -1.0f + (float)y * STEP;
    const float px = -1.0f + (float)tid * STEP;

    ull acc2 = 0ULL;
    const float* xp = x + (((size_t)b << 22) | ((size_t)y << 8)) + tid;
    const ull* wp = (const ull*)swd;
    #pragma unroll 8
    for (int c = 0; c < 64; c++) {
        float v = xp[(size_t)c << 16];
        ull vv; DUP2(vv, v);
        FMA2(acc2, vv, wp[c], acc2);
    }
    float s, d;
    UNPACK2(s, d, acc2);
    s += fmaf(py, sc[0], fmaf(px, sc[1], sc[2]));
    d += fmaf(py, sc[3], fmaf(px, sc[4], sc[5]));

    const int node = (b << 16) + (y << 8) + tid;
    g_asrc[node] = s;
    g_adst[node] = d;
}

// ---------------------------------------------------------------------------
// mma helpers (base PTX, sm_80+)
// ---------------------------------------------------------------------------
__device__ __forceinline__ uint32_t smem_u32(const void* p) {
    uint32_t r;
    asm("{ .reg .u64 t; cvta.to.shared.u64 t, %1; cvt.u32.u64 %0, t; }"
        : "=r"(r) : "l"(p));
    return r;
}
__device__ __forceinline__ void ldm_x4(uint32_t* r, uint32_t a) {
    asm volatile("ldmatrix.sync.aligned.m8n8.x4.shared.b16 {%0,%1,%2,%3}, [%4];"
        : "=r"(r[0]), "=r"(r[1]), "=r"(r[2]), "=r"(r[3]) : "r"(a));
}
__device__ __forceinline__ void ldm_x4_t(uint32_t* r, uint32_t a) {
    asm volatile("ldmatrix.sync.aligned.m8n8.x4.trans.shared.b16 {%0,%1,%2,%3}, [%4];"
        : "=r"(r[0]), "=r"(r[1]), "=r"(r[2]), "=r"(r[3]) : "r"(a));
}
__device__ __forceinline__ void mma16816(float* c, const uint32_t* a,
                                         uint32_t b0, uint32_t b1) {
    asm volatile(
        "mma.sync.aligned.m16n8k16.row.col.f32.bf16.bf16.f32 "
        "{%0,%1,%2,%3}, {%4,%5,%6,%7}, {%8,%9}, {%0,%1,%2,%3};"
        : "+f"(c[0]), "+f"(c[1]), "+f"(c[2]), "+f"(c[3])
        : "r"(a[0]), "r"(a[1]), "r"(a[2]), "r"(a[3]), "r"(b0), "r"(b1));
}

#define ZPITCH 272   // z tiles [c=64][x=128] bf16: 256B data + 16B pad
#define WPITCH 144   // W tiles [co=64][k=64] bf16: 128B data + 16B pad

// ---------------------------------------------------------------------------
// K2: fused. block = 128 x of one (b,y) row, 256 threads.
//   Agg (R6 winner): thread = (x, channel-half); alpha in regs via direct
//   LDG; 9 clamped scalar LDGs per channel; z split bf16 hi/lo -> STS.16
//   into zh/zl tiles. One barrier. HMMA GEMM + epilogue (R11, verified).
// ---------------------------------------------------------------------------
__global__ __launch_bounds__(256) void gat_k2(
    const float* __restrict__ x,
    const float* __restrict__ lin_w,
    const float* __restrict__ pos_w,
    const float* __restrict__ pos_b,
    const float* __restrict__ bias,
    float* __restrict__ out)
{
    __shared__ __align__(16) char tileblob[2 * 64 * ZPITCH];  // zh, zl; later staging
    __shared__ __align__(16) char wblob[2 * 64 * WPITCH];     // Wh, Wl
    __shared__ float pw0[64], pw1[64], pb_s[64], b_s[64];

    const int tid  = threadIdx.x;
    const int lane = tid & 31;
    const int wid  = tid >> 5;
    const int blk  = blockIdx.x;       // 1024
    const int b  = blk >> 9;
    const int r  = blk & 511;
    const int y  = r >> 1;
    const int x0 = (r & 1) << 7;

    char* zh_c = tileblob;
    char* zl_c = tileblob + 64 * ZPITCH;
    char* wh_c = wblob;
    char* wl_c = wblob + 64 * WPITCH;

    if (tid < 64) {
        pw0[tid]  = pos_w[tid];
        pw1[tid]  = pos_w[64 + tid];
        pb_s[tid] = pos_b[tid];
        b_s[tid]  = bias[tid];
    }

    // ---- stage W hi/lo: Wh/Wl[co][k] ----
    {
        const int co = tid & 63;
        const int kq = tid >> 6;
        const float* wp = lin_w + co;
        #pragma unroll
        for (int j = 0; j < 8; j++) {
            const int k0 = kq * 16 + 2 * j;
            float w0 = wp[(size_t)k0 * 64];
            float w1 = wp[(size_t)(k0 + 1) * 64];
            __nv_bfloat162 h = __float22bfloat162_rn(make_float2(w0, w1));
            *(uint32_t*)(wh_c + co * WPITCH + k0 * 2) = *(uint32_t*)&h;
            float r0 = w0 - __bfloat162float(h.x);
            float r1 = w1 - __bfloat162float(h.y);
            __nv_bfloat162 l = __float22bfloat162_rn(make_float2(r0, r1));
            *(uint32_t*)(wl_c + co * WPITCH + k0 * 2) = *(uint32_t*)&l;
        }
    }

    // ---- aggregation (R6 structure) ----
    const int seg  = wid & 3;
    const int half = wid >> 2;          // channel half: 0 or 1
    const int xl   = seg * 32 + lane;   // local x 0..127
    const int xd   = x0 + xl;

    // alpha in regs (direct LDG for a_src halo)
    float alpha[9];
    {
        const float ad = g_adst[(b << 16) + (y << 8) + xd];
        float m = -1e30f;
        #pragma unroll
        for (int ry = 0; ry < 3; ry++) {
            const int yy = y - 1 + ry;
            const bool rok = (unsigned)yy < 256u;
            #pragma unroll
            for (int cx = 0; cx < 3; cx++) {
                const int xs = xd - 1 + cx;
                float as = -1e30f;
                if (rok && (unsigned)xs < 256u)
                    as = g_asrc[(b << 16) + (yy << 8) + xs];
                float e = as + ad;
                e = (e >= 0.0f) ? e : NEG_SLOPE * e;
                alpha[ry * 3 + cx] = e;
                m = fmaxf(m, e);
            }
        }
        float ssum = 0.0f;
        #pragma unroll
        for (int j = 0; j < 9; j++) {
            float p = expf(alpha[j] - m);
            alpha[j] = p;
            ssum += p;
        }
        const float inv = 1.0f / ssum;
        #pragma unroll
        for (int j = 0; j < 9; j++) alpha[j] *= inv;
    }

    // PE hoist
    float sumpy = 0.0f, sumpx = 0.0f;
    #pragma unroll
    for (int ry = 0; ry < 3; ry++) {
        const float pyv = -1.0f + (float)(y - 1 + ry) * STEP;
        #pragma unroll
        for (int cx = 0; cx < 3; cx++) {
            const float pxv = -1.0f + (float)(xd - 1 + cx) * STEP;
            sumpy = fmaf(alpha[ry * 3 + cx], pyv, sumpy);
            sumpx = fmaf(alpha[ry * 3 + cx], pxv, sumpx);
        }
    }

    // clamped row/col offsets (invalid -> alpha==0 exact)
    int ro[3];
    #pragma unroll
    for (int ry = 0; ry < 3; ry++) {
        int yy = y - 1 + ry;
        ro[ry] = (yy < 0 ? 0 : (yy > 255 ? 255 : yy)) << 8;
    }
    const int xm  = (xd - 1 < 0)   ? 0   : xd - 1;
    const int xpp = (xd + 1 > 255) ? 255 : xd + 1;

    const float* bb = x + ((size_t)b << 22) + ((size_t)(half << 5) << 16);
    const float* p00 = bb + ro[0] + xm;
    const float* p01 = bb + ro[0] + xd;
    const float* p02 = bb + ro[0] + xpp;
    const float* p10 = bb + ro[1] + xm;
    const float* p11 = bb + ro[1] + xd;
    const float* p12 = bb + ro[1] + xpp;
    const float* p20 = bb + ro[2] + xm;
    const float* p21 = bb + ro[2] + xd;
    const float* p22 = bb + ro[2] + xpp;

    #pragma unroll 8
    for (int ci = 0; ci < 32; ci++) {
        const int c = (half << 5) + ci;
        const size_t co = (size_t)ci << 16;
        const float v00 = p00[co], v01 = p01[co], v02 = p02[co];
        const float v10 = p10[co], v11 = p11[co], v12 = p12[co];
        const float v20 = p20[co], v21 = p21[co], v22 = p22[co];

        float zacc = fmaf(pw0[c], sumpy, fmaf(pw1[c], sumpx, pb_s[c]));
        zacc = fmaf(alpha[0], v00, zacc);
        zacc = fmaf(alpha[1], v01, zacc);
        zacc = fmaf(alpha[2], v02, zacc);
        zacc = fmaf(alpha[3], v10, zacc);
        zacc = fmaf(alpha[4], v11, zacc);
        zacc = fmaf(alpha[5], v12, zacc);
        zacc = fmaf(alpha[6], v20, zacc);
        zacc = fmaf(alpha[7], v21, zacc);
        zacc = fmaf(alpha[8], v22, zacc);

        // split to bf16 hi + residual, STS.16 into tiles [c][x]
        __nv_bfloat16 h = __float2bfloat16(zacc);
        __nv_bfloat16 l = __float2bfloat16(zacc - __bfloat162float(h));
        *(__nv_bfloat16*)(zh_c + c * ZPITCH + xl * 2) = h;
        *(__nv_bfloat16*)(zl_c + c * ZPITCH + xl * 2) = l;
    }
    __syncthreads();

    // ---- HMMA GEMM (R11, verified) ----
    const int m0 = (wid & 3) << 4;
    const int nb = (wid >> 2) << 6;

    const uint32_t zh_b = smem_u32(zh_c);
    const uint32_t zl_b = smem_u32(zl_c);
    const uint32_t wh_b = smem_u32(wh_c);
    const uint32_t wl_b = smem_u32(wl_c);

    const uint32_t w_row = (uint32_t)(m0 + (lane & 15)) * WPITCH;
    const uint32_t w_kad = ((lane >> 4) << 3) * 2;
    const uint32_t z_kro = (uint32_t)(lane & 15) * ZPITCH;
    const uint32_t z_nad = ((lane >> 4) << 3) * 2;

    float acc[8][4];
    #pragma unroll
    for (int i = 0; i < 8; i++)
        #pragma unroll
        for (int j = 0; j < 4; j++) acc[i][j] = 0.0f;

    #pragma unroll
    for (int ks = 0; ks < 4; ks++) {
        const int k0 = ks << 4;
        uint32_t ah[4], al[4];
        ldm_x4(ah, wh_b + w_row + (uint32_t)k0 * 2 + w_kad);
        ldm_x4(al, wl_b + w_row + (uint32_t)k0 * 2 + w_kad);

        #pragma unroll
        for (int np = 0; np < 4; np++) {
            const uint32_t n0 = nb + (np << 4);
            const uint32_t zoff = (uint32_t)k0 * ZPITCH + z_kro + n0 * 2 + z_nad;
            uint32_t bh[4], bl[4];
            ldm_x4_t(bh, zh_b + zoff);
            ldm_x4_t(bl, zl_b + zoff);
            mma16816(acc[2 * np],     ah, bh[0], bh[1]);
            mma16816(acc[2 * np + 1], ah, bh[2], bh[3]);
            mma16816(acc[2 * np],     ah, bl[0], bl[1]);
            mma16816(acc[2 * np + 1], ah, bl[2], bl[3]);
            mma16816(acc[2 * np],     al, bh[0], bh[1]);
            mma16816(acc[2 * np + 1], al, bh[2], bh[3]);
        }
    }
    __syncthreads();

    // ---- epilogue: frags -> staging [co][x] (pitch 132 floats) ----
    float* stage = (float*)tileblob;
    {
        const int co_r = m0 + (lane >> 2);
        #pragma unroll
        for (int nt = 0; nt < 8; nt++) {
            const int xb = nb + nt * 8 + 2 * (lane & 3);
            *(float2*)&stage[co_r * 132 + xb]       = make_float2(acc[nt][0], acc[nt][1]);
            *(float2*)&stage[(co_r + 8) * 132 + xb] = make_float2(acc[nt][2], acc[nt][3]);
        }
    }
    __syncthreads();

    {
        const int xq = lane;
        float* ob = out + ((size_t)b << 22) + (y << 8) + x0 + 4 * xq;
        #pragma unroll
        for (int it = 0; it < 8; it++) {
            const int co = wid + it * 8;
            float4 v = *(const float4*)&stage[co * 132 + 4 * xq];
            const float bv = b_s[co];
            v.x += bv; v.y += bv; v.z += bv; v.w += bv;
            *(float4*)(ob + ((size_t)co << 16)) = v;
        }
    }
}

// ---------------------------------------------------------------------------
extern "C" void kernel_launch(void* const* d_in, const int* in_sizes, int n_in,
                              void* d_out, int out_size)
{
    const float* x       = (const float*)d_in[0];
    const float* pos_w   = (const float*)d_in[1];
    const float* pos_b   = (const float*)d_in[2];
    const float* lin_w   = (const float*)d_in[3];
    const float* att_src = (const float*)d_in[4];
    const float* att_dst = (const float*)d_in[5];
    const float* bias    = (const float*)d_in[6];
    float* out = (float*)d_out;

    gat_k1<<<512, 256>>>(x, pos_w, pos_b, lin_w, att_src, att_dst);
    gat_k2<<<1024, 256>>>(x, lin_w, pos_w, pos_b, bias, out);
}

// round 13
// speedup vs baseline: 1.6805x; 1.0091x over previous
#include <cuda_runtime.h>
#include <cuda_bf16.h>
#include <cstdint>

#define NEG_SLOPE 0.2f
#define STEP (2.0f / 255.0f)

typedef unsigned long long ull;

__device__ float g_asrc[131072];
__device__ float g_adst[131072];

#define FMA2(d, a, b, c) \
    asm("fma.rn.f32x2 %0, %1, %2, %3;" : "=l"(d) : "l"(a), "l"(b), "l"(c))
#define DUP2(d, s) \
    asm("mov.b64 %0, {%1, %1};" : "=l"(d) : "r"(__float_as_uint(s)))
#define UNPACK2(lo, hi, s) do { \
    unsigned _ulo, _uhi; \
    asm("mov.b64 {%0, %1}, %2;" : "=r"(_ulo), "=r"(_uhi) : "l"(s)); \
    lo = __uint_as_float(_ulo); hi = __uint_as_float(_uhi); } while (0)

// ---------------------------------------------------------------------------
// K1: per-node a_src = xg.(W@att_src), a_dst = xg.(W@att_dst)   (unchanged)
// ---------------------------------------------------------------------------
__global__ __launch_bounds__(256) void gat_k1(
    const float* __restrict__ x,
    const float* __restrict__ pos_w,
    const float* __restrict__ pos_b,
    const float* __restrict__ lin_w,
    const float* __restrict__ att_src,
    const float* __restrict__ att_dst)
{
    __shared__ float swd[128];
    __shared__ float as_s[64], ad_s[64];
    __shared__ float pw0[64], pw1[64], pb_s[64];
    __shared__ float sc[6];

    const int tid = threadIdx.x;
    const int row = blockIdx.x;
    const int b = row >> 8;
    const int y = row & 255;

    if (tid < 64) {
        as_s[tid] = att_src[tid];
        ad_s[tid] = att_dst[tid];
        pw0[tid]  = pos_w[tid];
        pw1[tid]  = pos_w[64 + tid];
        pb_s[tid] = pos_b[tid];
    }
    __syncthreads();

    if (tid < 64) {
        float s = 0.0f, d = 0.0f;
        const float* lw = lin_w + tid * 64;
        #pragma unroll 8
        for (int co = 0; co < 64; co++) {
            float w = lw[co];
            s = fmaf(w, as_s[co], s);
            d = fmaf(w, ad_s[co], d);
        }
        swd[2 * tid]     = s;
        swd[2 * tid + 1] = d;
    }
    __syncthreads();

    if (tid < 6) {
        const int which = tid % 3;
        const int off   = (tid < 3) ? 0 : 1;
        const float* pv = (which == 0) ? pw0 : (which == 1) ? pw1 : pb_s;
        float acc = 0.0f;
        #pragma unroll 8
        for (int c = 0; c < 64; c++)
            acc = fmaf(pv[c], swd[2 * c + off], acc);
        sc[tid] = acc;
    }
    __syncthreads();

    const float py = -1.0f + (float)y * STEP;
    const float px = -1.0f + (float)tid * STEP;

    ull acc2 = 0ULL;
    const float* xp = x + (((size_t)b << 22) | ((size_t)y << 8)) + tid;
    const ull* wp = (const ull*)swd;
    #pragma unroll 8
    for (int c = 0; c < 64; c++) {
        float v = xp[(size_t)c << 16];
        ull vv; DUP2(vv, v);
        FMA2(acc2, vv, wp[c], acc2);
    }
    float s, d;
    UNPACK2(s, d, acc2);
    s += fmaf(py, sc[0], fmaf(px, sc[1], sc[2]));
    d += fmaf(py, sc[3], fmaf(px, sc[4], sc[5]));

    const int node = (b << 16) + (y << 8) + tid;
    g_asrc[node] = s;
    g_adst[node] = d;
}

// ---------------------------------------------------------------------------
// mma helpers (base PTX, sm_80+)
// ---------------------------------------------------------------------------
__device__ __forceinline__ uint32_t smem_u32(const void* p) {
    uint32_t r;
    asm("{ .reg .u64 t; cvta.to.shared.u64 t, %1; cvt.u32.u64 %0, t; }"
        : "=r"(r) : "l"(p));
    return r;
}
__device__ __forceinline__ void ldm_x4(uint32_t* r, uint32_t a) {
    asm volatile("ldmatrix.sync.aligned.m8n8.x4.shared.b16 {%0,%1,%2,%3}, [%4];"
        : "=r"(r[0]), "=r"(r[1]), "=r"(r[2]), "=r"(r[3]) : "r"(a));
}
__device__ __forceinline__ void ldm_x4_t(uint32_t* r, uint32_t a) {
    asm volatile("ldmatrix.sync.aligned.m8n8.x4.trans.shared.b16 {%0,%1,%2,%3}, [%4];"
        : "=r"(r[0]), "=r"(r[1]), "=r"(r[2]), "=r"(r[3]) : "r"(a));
}
__device__ __forceinline__ void mma16816(float* c, const uint32_t* a,
                                         uint32_t b0, uint32_t b1) {
    asm volatile(
        "mma.sync.aligned.m16n8k16.row.col.f32.bf16.bf16.f32 "
        "{%0,%1,%2,%3}, {%4,%5,%6,%7}, {%8,%9}, {%0,%1,%2,%3};"
        : "+f"(c[0]), "+f"(c[1]), "+f"(c[2]), "+f"(c[3])
        : "r"(a[0]), "r"(a[1]), "r"(a[2]), "r"(a[3]), "r"(b0), "r"(b1));
}

#define ZPITCH 272   // z tiles [c=64][x=128] bf16: 256B data + 16B pad
#define WPITCH 144   // W tiles [co=64][k=64] bf16: 128B data + 16B pad

// ---------------------------------------------------------------------------
// K2: fused. block = 128 x of one (b,y) row, 256 threads.
//   Agg (R6 winner): alpha in regs via direct LDG; 9 clamped scalar LDGs per
//   channel; z split bf16 hi/lo -> zh/zl tiles. RACE FIX: barrier before the
//   aggregation reads pw0/pw1/pb_s. HMMA GEMM; DIRECT-STG epilogue.
// ---------------------------------------------------------------------------
__global__ __launch_bounds__(256) void gat_k2(
    const float* __restrict__ x,
    const float* __restrict__ lin_w,
    const float* __restrict__ pos_w,
    const float* __restrict__ pos_b,
    const float* __restrict__ bias,
    float* __restrict__ out)
{
    __shared__ __align__(16) char tileblob[2 * 64 * ZPITCH];  // zh, zl
    __shared__ __align__(16) char wblob[2 * 64 * WPITCH];     // Wh, Wl
    __shared__ float pw0[64], pw1[64], pb_s[64], b_s[64];

    const int tid  = threadIdx.x;
    const int lane = tid & 31;
    const int wid  = tid >> 5;
    const int blk  = blockIdx.x;       // 1024
    const int b  = blk >> 9;
    const int r  = blk & 511;
    const int y  = r >> 1;
    const int x0 = (r & 1) << 7;

    char* zh_c = tileblob;
    char* zl_c = tileblob + 64 * ZPITCH;
    char* wh_c = wblob;
    char* wl_c = wblob + 64 * WPITCH;

    if (tid < 64) {
        pw0[tid]  = pos_w[tid];
        pw1[tid]  = pos_w[64 + tid];
        pb_s[tid] = pos_b[tid];
        b_s[tid]  = bias[tid];
    }

    // ---- stage W hi/lo: Wh/Wl[co][k] ----
    {
        const int co = tid & 63;
        const int kq = tid >> 6;
        const float* wp = lin_w + co;
        #pragma unroll
        for (int j = 0; j < 8; j++) {
            const int k0 = kq * 16 + 2 * j;
            float w0 = wp[(size_t)k0 * 64];
            float w1 = wp[(size_t)(k0 + 1) * 64];
            __nv_bfloat162 h = __float22bfloat162_rn(make_float2(w0, w1));
            *(uint32_t*)(wh_c + co * WPITCH + k0 * 2) = *(uint32_t*)&h;
            float r0 = w0 - __bfloat162float(h.x);
            float r1 = w1 - __bfloat162float(h.y);
            __nv_bfloat162 l = __float22bfloat162_rn(make_float2(r0, r1));
            *(uint32_t*)(wl_c + co * WPITCH + k0 * 2) = *(uint32_t*)&l;
        }
    }

    // ---- aggregation setup (no smem reads yet) ----
    const int seg  = wid & 3;
    const int half = wid >> 2;          // channel half: 0 or 1
    const int xl   = seg * 32 + lane;   // local x 0..127
    const int xd   = x0 + xl;

    // alpha in regs (direct LDG for a_src halo)
    float alpha[9];
    {
        const float ad = g_adst[(b << 16) + (y << 8) + xd];
        float m = -1e30f;
        #pragma unroll
        for (int ry = 0; ry < 3; ry++) {
            const int yy = y - 1 + ry;
            const bool rok = (unsigned)yy < 256u;
            #pragma unroll
            for (int cx = 0; cx < 3; cx++) {
                const int xs = xd - 1 + cx;
                float as = -1e30f;
                if (rok && (unsigned)xs < 256u)
                    as = g_asrc[(b << 16) + (yy << 8) + xs];
                float e = as + ad;
                e = (e >= 0.0f) ? e : NEG_SLOPE * e;
                alpha[ry * 3 + cx] = e;
                m = fmaxf(m, e);
            }
        }
        float ssum = 0.0f;
        #pragma unroll
        for (int j = 0; j < 9; j++) {
            float p = expf(alpha[j] - m);
            alpha[j] = p;
            ssum += p;
        }
        const float inv = 1.0f / ssum;
        #pragma unroll
        for (int j = 0; j < 9; j++) alpha[j] *= inv;
    }

    // PE hoist (no smem)
    float sumpy = 0.0f, sumpx = 0.0f;
    #pragma unroll
    for (int ry = 0; ry < 3; ry++) {
        const float pyv = -1.0f + (float)(y - 1 + ry) * STEP;
        #pragma unroll
        for (int cx = 0; cx < 3; cx++) {
            const float pxv = -1.0f + (float)(xd - 1 + cx) * STEP;
            sumpy = fmaf(alpha[ry * 3 + cx], pyv, sumpy);
            sumpx = fmaf(alpha[ry * 3 + cx], pxv, sumpx);
        }
    }

    // RACE FIX: pw0/pw1/pb_s (written by threads 0-63) are read below by all
    // threads; W staging must also be visible before GEMM (covered here too).
    __syncthreads();

    // clamped row/col offsets (invalid -> alpha==0 exact)
    int ro[3];
    #pragma unroll
    for (int ry = 0; ry < 3; ry++) {
        int yy = y - 1 + ry;
        ro[ry] = (yy < 0 ? 0 : (yy > 255 ? 255 : yy)) << 8;
    }
    const int xm  = (xd - 1 < 0)   ? 0   : xd - 1;
    const int xpp = (xd + 1 > 255) ? 255 : xd + 1;

    const float* bb = x + ((size_t)b << 22) + ((size_t)(half << 5) << 16);
    const float* p00 = bb + ro[0] + xm;
    const float* p01 = bb + ro[0] + xd;
    const float* p02 = bb + ro[0] + xpp;
    const float* p10 = bb + ro[1] + xm;
    const float* p11 = bb + ro[1] + xd;
    const float* p12 = bb + ro[1] + xpp;
    const float* p20 = bb + ro[2] + xm;
    const float* p21 = bb + ro[2] + xd;
    const float* p22 = bb + ro[2] + xpp;

    #pragma unroll 8
    for (int ci = 0; ci < 32; ci++) {
        const int c = (half << 5) + ci;
        const size_t co = (size_t)ci << 16;
        const float v00 = p00[co], v01 = p01[co], v02 = p02[co];
        const float v10 = p10[co], v11 = p11[co], v12 = p12[co];
        const float v20 = p20[co], v21 = p21[co], v22 = p22[co];

        float zacc = fmaf(pw0[c], sumpy, fmaf(pw1[c], sumpx, pb_s[c]));
        zacc = fmaf(alpha[0], v00, zacc);
        zacc = fmaf(alpha[1], v01, zacc);
        zacc = fmaf(alpha[2], v02, zacc);
        zacc = fmaf(alpha[3], v10, zacc);
        zacc = fmaf(alpha[4], v11, zacc);
        zacc = fmaf(alpha[5], v12, zacc);
        zacc = fmaf(alpha[6], v20, zacc);
        zacc = fmaf(alpha[7], v21, zacc);
        zacc = fmaf(alpha[8], v22, zacc);

        // split to bf16 hi + residual, STS.16 into tiles [c][x]
        __nv_bfloat16 h = __float2bfloat16(zacc);
        __nv_bfloat16 l = __float2bfloat16(zacc - __bfloat162float(h));
        *(__nv_bfloat16*)(zh_c + c * ZPITCH + xl * 2) = h;
        *(__nv_bfloat16*)(zl_c + c * ZPITCH + xl * 2) = l;
    }
    __syncthreads();

    // ---- HMMA GEMM ----
    const int m0 = (wid & 3) << 4;
    const int nb = (wid >> 2) << 6;

    const uint32_t zh_b = smem_u32(zh_c);
    const uint32_t zl_b = smem_u32(zl_c);
    const uint32_t wh_b = smem_u32(wh_c);
    const uint32_t wl_b = smem_u32(wl_c);

    const uint32_t w_row = (uint32_t)(m0 + (lane & 15)) * WPITCH;
    const uint32_t w_kad = ((lane >> 4) << 3) * 2;
    const uint32_t z_kro = (uint32_t)(lane & 15) * ZPITCH;
    const uint32_t z_nad = ((lane >> 4) << 3) * 2;

    float acc[8][4];
    #pragma unroll
    for (int i = 0; i < 8; i++)
        #pragma unroll
        for (int j = 0; j < 4; j++) acc[i][j] = 0.0f;

    #pragma unroll
    for (int ks = 0; ks < 4; ks++) {
        const int k0 = ks << 4;
        uint32_t ah[4], al[4];
        ldm_x4(ah, wh_b + w_row + (uint32_t)k0 * 2 + w_kad);
        ldm_x4(al, wl_b + w_row + (uint32_t)k0 * 2 + w_kad);

        #pragma unroll
        for (int np = 0; np < 4; np++) {
            const uint32_t n0 = nb + (np << 4);
            const uint32_t zoff = (uint32_t)k0 * ZPITCH + z_kro + n0 * 2 + z_nad;
            uint32_t bh[4], bl[4];
            ldm_x4_t(bh, zh_b + zoff);
            ldm_x4_t(bl, zl_b + zoff);
            mma16816(acc[2 * np],     ah, bh[0], bh[1]);
            mma16816(acc[2 * np + 1], ah, bh[2], bh[3]);
            mma16816(acc[2 * np],     ah, bl[0], bl[1]);
            mma16816(acc[2 * np + 1], ah, bl[2], bl[3]);
            mma16816(acc[2 * np],     al, bh[0], bh[1]);
            mma16816(acc[2 * np + 1], al, bh[2], bh[3]);
        }
    }

    // ---- direct-STG epilogue: no staging, no barriers ----
    // acc[nt] covers x = nb + nt*8 + 2*(lane&3) + {0,1};
    // rows co_r = m0 + (lane>>2) and co_r + 8.
    {
        const int co_r = m0 + (lane >> 2);
        const float bv0 = b_s[co_r];
        const float bv1 = b_s[co_r + 8];
        float* ob = out + ((size_t)b << 22) + (y << 8) + x0;
        float* r0p = ob + ((size_t)co_r << 16);
        float* r1p = ob + ((size_t)(co_r + 8) << 16);
        #pragma unroll
        for (int nt = 0; nt < 8; nt++) {
            const int xb = nb + nt * 8 + 2 * (lane & 3);
            *(float2*)(r0p + xb) = make_float2(acc[nt][0] + bv0, acc[nt][1] + bv0);
            *(float2*)(r1p + xb) = make_float2(acc[nt][2] + bv1, acc[nt][3] + bv1);
        }
    }
}

// ---------------------------------------------------------------------------
extern "C" void kernel_launch(void* const* d_in, const int* in_sizes, int n_in,
                              void* d_out, int out_size)
{
    const float* x       = (const float*)d_in[0];
    const float* pos_w   = (const float*)d_in[1];
    const float* pos_b   = (const float*)d_in[2];
    const float* lin_w   = (const float*)d_in[3];
    const float* att_src = (const float*)d_in[4];
    const float* att_dst = (const float*)d_in[5];
    const float* bias    = (const float*)d_in[6];
    float* out = (float*)d_out;

    gat_k1<<<512, 256>>>(x, pos_w, pos_b, lin_w, att_src, att_dst);
    gat_k2<<<1024, 256>>>(x, lin_w, pos_w, pos_b, bias, out);
}

// round 14
// speedup vs baseline: 1.8139x; 1.0794x over previous
#include <cuda_runtime.h>
#include <cuda_bf16.h>
#include <cstdint>

#define NEG_SLOPE 0.2f
#define STEP (2.0f / 255.0f)

typedef unsigned long long ull;

__device__ float g_asrc[131072];
__device__ float g_adst[131072];

#define FMA2(d, a, b, c) \
    asm("fma.rn.f32x2 %0, %1, %2, %3;" : "=l"(d) : "l"(a), "l"(b), "l"(c))
#define DUP2(d, s) \
    asm("mov.b64 %0, {%1, %1};" : "=l"(d) : "r"(__float_as_uint(s)))
#define UNPACK2(lo, hi, s) do { \
    unsigned _ulo, _uhi; \
    asm("mov.b64 {%0, %1}, %2;" : "=r"(_ulo), "=r"(_uhi) : "l"(s)); \
    lo = __uint_as_float(_ulo); hi = __uint_as_float(_uhi); } while (0)

// ---------------------------------------------------------------------------
// K1: per-node a_src = xg.(W@att_src), a_dst = xg.(W@att_dst)   (unchanged)
// ---------------------------------------------------------------------------
__global__ __launch_bounds__(256) void gat_k1(
    const float* __restrict__ x,
    const float* __restrict__ pos_w,
    const float* __restrict__ pos_b,
    const float* __restrict__ lin_w,
    const float* __restrict__ att_src,
    const float* __restrict__ att_dst)
{
    __shared__ float swd[128];
    __shared__ float as_s[64], ad_s[64];
    __shared__ float pw0[64], pw1[64], pb_s[64];
    __shared__ float sc[6];

    const int tid = threadIdx.x;
    const int row = blockIdx.x;
    const int b = row >> 8;
    const int y = row & 255;

    if (tid < 64) {
        as_s[tid] = att_src[tid];
        ad_s[tid] = att_dst[tid];
        pw0[tid]  = pos_w[tid];
        pw1[tid]  = pos_w[64 + tid];
        pb_s[tid] = pos_b[tid];
    }
    __syncthreads();

    if (tid < 64) {
        float s = 0.0f, d = 0.0f;
        const float* lw = lin_w + tid * 64;
        #pragma unroll 8
        for (int co = 0; co < 64; co++) {
            float w = lw[co];
            s = fmaf(w, as_s[co], s);
            d = fmaf(w, ad_s[co], d);
        }
        swd[2 * tid]     = s;
        swd[2 * tid + 1] = d;
    }
    __syncthreads();

    if (tid < 6) {
        const int which = tid % 3;
        const int off   = (tid < 3) ? 0 : 1;
        const float* pv = (which == 0) ? pw0 : (which == 1) ? pw1 : pb_s;
        float acc = 0.0f;
        #pragma unroll 8
        for (int c = 0; c < 64; c++)
            acc = fmaf(pv[c], swd[2 * c + off], acc);
        sc[tid] = acc;
    }
    __syncthreads();

    const float py = -1.0f + (float)y * STEP;
    const float px = -1.0f + (float)tid * STEP;

    ull acc2 = 0ULL;
    const float* xp = x + (((size_t)b << 22) | ((size_t)y << 8)) + tid;
    const ull* wp = (const ull*)swd;
    #pragma unroll 8
    for (int c = 0; c < 64; c++) {
        float v = xp[(size_t)c << 16];
        ull vv; DUP2(vv, v);
        FMA2(acc2, vv, wp[c], acc2);
    }
    float s, d;
    UNPACK2(s, d, acc2);
    s += fmaf(py, sc[0], fmaf(px, sc[1], sc[2]));
    d += fmaf(py, sc[3], fmaf(px, sc[4], sc[5]));

    const int node = (b << 16) + (y << 8) + tid;
    g_asrc[node] = s;
    g_adst[node] = d;
}

// ---------------------------------------------------------------------------
// mma helpers (base PTX, sm_80+)
// ---------------------------------------------------------------------------
__device__ __forceinline__ uint32_t smem_u32(const void* p) {
    uint32_t r;
    asm("{ .reg .u64 t; cvta.to.shared.u64 t, %1; cvt.u32.u64 %0, t; }"
        : "=r"(r) : "l"(p));
    return r;
}
__device__ __forceinline__ void ldm_x4(uint32_t* r, uint32_t a) {
    asm volatile("ldmatrix.sync.aligned.m8n8.x4.shared.b16 {%0,%1,%2,%3}, [%4];"
        : "=r"(r[0]), "=r"(r[1]), "=r"(r[2]), "=r"(r[3]) : "r"(a));
}
__device__ __forceinline__ void ldm_x4_t(uint32_t* r, uint32_t a) {
    asm volatile("ldmatrix.sync.aligned.m8n8.x4.trans.shared.b16 {%0,%1,%2,%3}, [%4];"
        : "=r"(r[0]), "=r"(r[1]), "=r"(r[2]), "=r"(r[3]) : "r"(a));
}
__device__ __forceinline__ void mma16816(float* c, const uint32_t* a,
                                         uint32_t b0, uint32_t b1) {
    asm volatile(
        "mma.sync.aligned.m16n8k16.row.col.f32.bf16.bf16.f32 "
        "{%0,%1,%2,%3}, {%4,%5,%6,%7}, {%8,%9}, {%0,%1,%2,%3};"
        : "+f"(c[0]), "+f"(c[1]), "+f"(c[2]), "+f"(c[3])
        : "r"(a[0]), "r"(a[1]), "r"(a[2]), "r"(a[3]), "r"(b0), "r"(b1));
}

#define ZPITCH 272   // z tiles [c=64][node=128] bf16: 256B data + 16B pad
#define WPITCH 144   // W tiles [co=64][k=64] bf16: 128B data + 16B pad

// ---------------------------------------------------------------------------
// K2: fused, 2-ROW TILES. block = 64 x * 2 y rows = 128 nodes, 256 threads.
//   Thread = (x, 16 channels, both y rows): per channel loads 4 rows x 3 cols
//   (12 LDG) and produces 2 outputs -> 6 LDG/output (was 9). z tile layout
//   [c][node], node = (y-y0)*64 + xl, so the HMMA GEMM + direct-STG epilogue
//   carry over unchanged (row = node>>6).
// ---------------------------------------------------------------------------
__global__ __launch_bounds__(256) void gat_k2(
    const float* __restrict__ x,
    const float* __restrict__ lin_w,
    const float* __restrict__ pos_w,
    const float* __restrict__ pos_b,
    const float* __restrict__ bias,
    float* __restrict__ out)
{
    __shared__ __align__(16) char tileblob[2 * 64 * ZPITCH];  // zh, zl
    __shared__ __align__(16) char wblob[2 * 64 * WPITCH];     // Wh, Wl
    __shared__ float pw0[64], pw1[64], pb_s[64], b_s[64];

    const int tid  = threadIdx.x;
    const int lane = tid & 31;
    const int wid  = tid >> 5;
    const int blk  = blockIdx.x;        // 1024
    const int b   = blk >> 9;
    const int rem = blk & 511;          // 128 y-pairs * 4 x-tiles
    const int y0  = (rem >> 2) << 1;    // even row
    const int x0g = (rem & 3) << 6;     // x tile base (64 wide)

    char* zh_c = tileblob;
    char* zl_c = tileblob + 64 * ZPITCH;
    char* wh_c = wblob;
    char* wl_c = wblob + 64 * WPITCH;

    if (tid < 64) {
        pw0[tid]  = pos_w[tid];
        pw1[tid]  = pos_w[64 + tid];
        pb_s[tid] = pos_b[tid];
        b_s[tid]  = bias[tid];
    }

    // ---- stage W hi/lo: Wh/Wl[co][k] ----
    {
        const int co = tid & 63;
        const int kq = tid >> 6;
        const float* wp = lin_w + co;
        #pragma unroll
        for (int j = 0; j < 8; j++) {
            const int k0 = kq * 16 + 2 * j;
            float w0 = wp[(size_t)k0 * 64];
            float w1 = wp[(size_t)(k0 + 1) * 64];
            __nv_bfloat162 h = __float22bfloat162_rn(make_float2(w0, w1));
            *(uint32_t*)(wh_c + co * WPITCH + k0 * 2) = *(uint32_t*)&h;
            float r0 = w0 - __bfloat162float(h.x);
            float r1 = w1 - __bfloat162float(h.y);
            __nv_bfloat162 l = __float22bfloat162_rn(make_float2(r0, r1));
            *(uint32_t*)(wl_c + co * WPITCH + k0 * 2) = *(uint32_t*)&l;
        }
    }

    // ---- per-thread geometry ----
    const int q  = tid >> 6;            // channel quarter (16 ch)
    const int xl = tid & 63;            // x within tile
    const int xd = x0g + xl;            // global x

    // ---- alpha for both rows (regs), from direct LDG ----
    float alpha0[9], alpha1[9];
    {
        float as_v[4][3];
        #pragma unroll
        for (int rr = 0; rr < 4; rr++) {
            const int yy = y0 - 1 + rr;
            const bool rok = (unsigned)yy < 256u;
            #pragma unroll
            for (int cx = 0; cx < 3; cx++) {
                const int xs = xd - 1 + cx;
                float v = -1e30f;
                if (rok && (unsigned)xs < 256u)
                    v = g_asrc[(b << 16) + (yy << 8) + xs];
                as_v[rr][cx] = v;
            }
        }
        const float ad0 = g_adst[(b << 16) + (y0 << 8) + xd];
        const float ad1 = g_adst[(b << 16) + ((y0 + 1) << 8) + xd];

        float m0 = -1e30f, m1 = -1e30f;
        #pragma unroll
        for (int ry = 0; ry < 3; ry++) {
            #pragma unroll
            for (int cx = 0; cx < 3; cx++) {
                float e0 = as_v[ry][cx] + ad0;
                e0 = (e0 >= 0.0f) ? e0 : NEG_SLOPE * e0;
                alpha0[ry * 3 + cx] = e0;
                m0 = fmaxf(m0, e0);
                float e1 = as_v[ry + 1][cx] + ad1;
                e1 = (e1 >= 0.0f) ? e1 : NEG_SLOPE * e1;
                alpha1[ry * 3 + cx] = e1;
                m1 = fmaxf(m1, e1);
            }
        }
        float s0 = 0.0f, s1 = 0.0f;
        #pragma unroll
        for (int j = 0; j < 9; j++) {
            float p0 = expf(alpha0[j] - m0);
            float p1 = expf(alpha1[j] - m1);
            alpha0[j] = p0; alpha1[j] = p1;
            s0 += p0; s1 += p1;
        }
        const float i0 = 1.0f / s0, i1 = 1.0f / s1;
        #pragma unroll
        for (int j = 0; j < 9; j++) { alpha0[j] *= i0; alpha1[j] *= i1; }
    }

    // ---- PE hoist for both rows ----
    float spy0 = 0.0f, spx0 = 0.0f, spy1 = 0.0f, spx1 = 0.0f;
    #pragma unroll
    for (int ry = 0; ry < 3; ry++) {
        const float py0v = -1.0f + (float)(y0 - 1 + ry) * STEP;
        const float py1v = -1.0f + (float)(y0 + ry) * STEP;
        #pragma unroll
        for (int cx = 0; cx < 3; cx++) {
            const float pxv = -1.0f + (float)(xd - 1 + cx) * STEP;
            spy0 = fmaf(alpha0[ry * 3 + cx], py0v, spy0);
            spx0 = fmaf(alpha0[ry * 3 + cx], pxv,  spx0);
            spy1 = fmaf(alpha1[ry * 3 + cx], py1v, spy1);
            spx1 = fmaf(alpha1[ry * 3 + cx], pxv,  spx1);
        }
    }

    // smem written by threads 0-63 (pw*/pb/b) read below by all threads
    __syncthreads();

    // ---- row offsets: rows y0,y0+1 always valid; clamp outer rows ----
    const int ot = (y0 == 0)   ? 0   : -256;   // row y0-1 (clamped)
    const int ob = (y0 == 254) ? 256 : 512;    // row y0+2 (clamped), from y0
    const int xm  = (xd - 1 < 0)   ? 0   : xd - 1;
    const int xpp = (xd + 1 > 255) ? 255 : xd + 1;

    const float* cbase = x + ((size_t)b << 22) + ((size_t)(q << 4) << 16)
                       + ((size_t)y0 << 8);
    #pragma unroll 4
    for (int ci = 0; ci < 16; ci++) {
        const int c = (q << 4) + ci;
        const float* cp = cbase + ((size_t)ci << 16);
        const float* pm = cp + xm;
        const float* pc = cp + xd;
        const float* pp = cp + xpp;

        // 4 rows x 3 cols
        const float v00 = pm[ot],  v01 = pc[ot],  v02 = pp[ot];
        const float v10 = pm[0],   v11 = pc[0],   v12 = pp[0];
        const float v20 = pm[256], v21 = pc[256], v22 = pp[256];
        const float v30 = pm[ob],  v31 = pc[ob],  v32 = pp[ob];

        float z0 = fmaf(pw0[c], spy0, fmaf(pw1[c], spx0, pb_s[c]));
        z0 = fmaf(alpha0[0], v00, z0);
        z0 = fmaf(alpha0[1], v01, z0);
        z0 = fmaf(alpha0[2], v02, z0);
        z0 = fmaf(alpha0[3], v10, z0);
        z0 = fmaf(alpha0[4], v11, z0);
        z0 = fmaf(alpha0[5], v12, z0);
        z0 = fmaf(alpha0[6], v20, z0);
        z0 = fmaf(alpha0[7], v21, z0);
        z0 = fmaf(alpha0[8], v22, z0);

        float z1 = fmaf(pw0[c], spy1, fmaf(pw1[c], spx1, pb_s[c]));
        z1 = fmaf(alpha1[0], v10, z1);
        z1 = fmaf(alpha1[1], v11, z1);
        z1 = fmaf(alpha1[2], v12, z1);
        z1 = fmaf(alpha1[3], v20, z1);
        z1 = fmaf(alpha1[4], v21, z1);
        z1 = fmaf(alpha1[5], v22, z1);
        z1 = fmaf(alpha1[6], v30, z1);
        z1 = fmaf(alpha1[7], v31, z1);
        z1 = fmaf(alpha1[8], v32, z1);

        // split to bf16 hi + residual; nodes: row0 -> xl, row1 -> 64+xl
        __nv_bfloat16 h0 = __float2bfloat16(z0);
        __nv_bfloat16 l0 = __float2bfloat16(z0 - __bfloat162float(h0));
        __nv_bfloat16 h1 = __float2bfloat16(z1);
        __nv_bfloat16 l1 = __float2bfloat16(z1 - __bfloat162float(h1));
        *(__nv_bfloat16*)(zh_c + c * ZPITCH + xl * 2)        = h0;
        *(__nv_bfloat16*)(zh_c + c * ZPITCH + (64 + xl) * 2) = h1;
        *(__nv_bfloat16*)(zl_c + c * ZPITCH + xl * 2)        = l0;
        *(__nv_bfloat16*)(zl_c + c * ZPITCH + (64 + xl) * 2) = l1;
    }
    __syncthreads();

    // ---- HMMA GEMM (verified) ----
    const int m0 = (wid & 3) << 4;
    const int nb = (wid >> 2) << 6;     // node base 0 (row y0) or 64 (row y0+1)

    const uint32_t zh_b = smem_u32(zh_c);
    const uint32_t zl_b = smem_u32(zl_c);
    const uint32_t wh_b = smem_u32(wh_c);
    const uint32_t wl_b = smem_u32(wl_c);

    const uint32_t w_row = (uint32_t)(m0 + (lane & 15)) * WPITCH;
    const uint32_t w_kad = ((lane >> 4) << 3) * 2;
    const uint32_t z_kro = (uint32_t)(lane & 15) * ZPITCH;
    const uint32_t z_nad = ((lane >> 4) << 3) * 2;

    float acc[8][4];
    #pragma unroll
    for (int i = 0; i < 8; i++)
        #pragma unroll
        for (int j = 0; j < 4; j++) acc[i][j] = 0.0f;

    #pragma unroll
    for (int ks = 0; ks < 4; ks++) {
        const int k0 = ks << 4;
        uint32_t ah[4], al[4];
        ldm_x4(ah, wh_b + w_row + (uint32_t)k0 * 2 + w_kad);
        ldm_x4(al, wl_b + w_row + (uint32_t)k0 * 2 + w_kad);

        #pragma unroll
        for (int np = 0; np < 4; np++) {
            const uint32_t n0 = nb + (np << 4);
            const uint32_t zoff = (uint32_t)k0 * ZPITCH + z_kro + n0 * 2 + z_nad;
            uint32_t bh[4], bl[4];
            ldm_x4_t(bh, zh_b + zoff);
            ldm_x4_t(bl, zl_b + zoff);
            mma16816(acc[2 * np],     ah, bh[0], bh[1]);
            mma16816(acc[2 * np + 1], ah, bh[2], bh[3]);
            mma16816(acc[2 * np],     ah, bl[0], bl[1]);
            mma16816(acc[2 * np + 1], ah, bl[2], bl[3]);
            mma16816(acc[2 * np],     al, bh[0], bh[1]);
            mma16816(acc[2 * np + 1], al, bh[2], bh[3]);
        }
    }

    // ---- direct-STG epilogue: node n = nb + nt*8 + 2*(lane&3) + {0,1} ----
    // row = y0 + (nb>>6); x = x0g + (n & 63)
    {
        const int co_r = m0 + (lane >> 2);
        const float bv0 = b_s[co_r];
        const float bv1 = b_s[co_r + 8];
        const int yrow = y0 + (nb >> 6);
        float* obp = out + ((size_t)b << 22) + (yrow << 8) + x0g;
        float* r0p = obp + ((size_t)co_r << 16);
        float* r1p = obp + ((size_t)(co_r + 8) << 16);
        #pragma unroll
        for (int nt = 0; nt < 8; nt++) {
            const int xb = nt * 8 + 2 * (lane & 3);
            *(float2*)(r0p + xb) = make_float2(acc[nt][0] + bv0, acc[nt][1] + bv0);
            *(float2*)(r1p + xb) = make_float2(acc[nt][2] + bv1, acc[nt][3] + bv1);
        }
    }
}

// ---------------------------------------------------------------------------
extern "C" void kernel_launch(void* const* d_in, const int* in_sizes, int n_in,
                              void* d_out, int out_size)
{
    const float* x       = (const float*)d_in[0];
    const float* pos_w   = (const float*)d_in[1];
    const float* pos_b   = (const float*)d_in[2];
    const float* lin_w   = (const float*)d_in[3];
    const float* att_src = (const float*)d_in[4];
    const float* att_dst = (const float*)d_in[5];
    const float* bias    = (const float*)d_in[6];
    float* out = (float*)d_out;

    gat_k1<<<512, 256>>>(x, pos_w, pos_b, lin_w, att_src, att_dst);
    gat_k2<<<1024, 256>>>(x, lin_w, pos_w, pos_b, bias, out);
}